// round 8
// baseline (speedup 1.0000x reference)
#include <cuda_runtime.h>
#include <cuda_fp16.h>
#include <cstdint>

#define NN 8192
#define DD 256

// ---------------- scratch (device globals; no allocation allowed) ----------
__device__ float  g_q[NN * DD];
__device__ float  g_v[NN * DD];
__device__ __half g_xh[NN * DD];              // x hi split
__device__ __half g_xl[NN * DD];              // x lo split
__device__ __half g_wh[3 * DD * DD];          // Wq|Wk|Wv hi split
__device__ __half g_wl[3 * DD * DD];          // Wq|Wk|Wv lo split
__device__ __half g_kh[NN * DD];              // k hi split [j][d]
__device__ __half g_kl[NN * DD];              // k lo split
__device__ float  g_spart[4 * NN];            // deterministic partials
__device__ float  g_s[NN];
__device__ float  g_alpha[NN];

// ---------------- PTX helpers (base sm_80+ ISA only) ------------------------
__device__ __forceinline__ uint32_t cvta_smem(const void* p) {
    uint32_t a;
    asm("{ .reg .u64 t; cvta.to.shared.u64 t, %1; cvt.u32.u64 %0, t; }"
        : "=r"(a) : "l"(p));
    return a;
}
__device__ __forceinline__ void cp16(uint32_t dst, const void* src) {
    asm volatile("cp.async.cg.shared.global [%0], [%1], 16;" :: "r"(dst), "l"(src));
}
__device__ __forceinline__ void cp_commit() {
    asm volatile("cp.async.commit_group;" ::: "memory");
}
template <int N>
__device__ __forceinline__ void cp_wait() {
    asm volatile("cp.async.wait_group %0;" :: "n"(N) : "memory");
}
__device__ __forceinline__ void ldm_x4(uint32_t addr, uint32_t& r0, uint32_t& r1,
                                       uint32_t& r2, uint32_t& r3) {
    asm volatile("ldmatrix.sync.aligned.m8n8.x4.shared.b16 {%0,%1,%2,%3}, [%4];"
                 : "=r"(r0), "=r"(r1), "=r"(r2), "=r"(r3) : "r"(addr));
}
__device__ __forceinline__ void ldm_x4_t(uint32_t addr, uint32_t& r0, uint32_t& r1,
                                         uint32_t& r2, uint32_t& r3) {
    asm volatile("ldmatrix.sync.aligned.m8n8.x4.trans.shared.b16 {%0,%1,%2,%3}, [%4];"
                 : "=r"(r0), "=r"(r1), "=r"(r2), "=r"(r3) : "r"(addr));
}
__device__ __forceinline__ void mma16816(float* c, const uint32_t* a,
                                         uint32_t b0, uint32_t b1) {
    asm volatile(
        "mma.sync.aligned.m16n8k16.row.col.f32.f16.f16.f32 "
        "{%0,%1,%2,%3}, {%4,%5,%6,%7}, {%8,%9}, {%0,%1,%2,%3};"
        : "+f"(c[0]), "+f"(c[1]), "+f"(c[2]), "+f"(c[3])
        : "r"(a[0]), "r"(a[1]), "r"(a[2]), "r"(a[3]), "r"(b0), "r"(b1));
}
__device__ __forceinline__ uint32_t pack_h2(float lo, float hi) {
    uint32_t r;
    asm("cvt.rn.f16x2.f32 %0, %1, %2;" : "=r"(r) : "f"(hi), "f"(lo));
    return r;
}

// ---------------------------------------------------------------------------
// Converters: x -> hi/lo, W -> hi/lo
// ---------------------------------------------------------------------------
__global__ __launch_bounds__(256) void xsplit_kernel(const float* __restrict__ x)
{
    size_t i4 = (size_t)blockIdx.x * blockDim.x + threadIdx.x;
    const size_t total4 = (size_t)NN * DD / 4;
    if (i4 >= total4) return;
    float4 xv = *(const float4*)(x + i4 * 4);
    float vs[4] = {xv.x, xv.y, xv.z, xv.w};
    __half hi[4], lo[4];
    #pragma unroll
    for (int i = 0; i < 4; i++) {
        hi[i] = __float2half_rn(vs[i]);
        lo[i] = __float2half_rn(vs[i] - __half2float(hi[i]));
    }
    *(__half2*)(g_xh + i4 * 4)     = __halves2half2(hi[0], hi[1]);
    *(__half2*)(g_xh + i4 * 4 + 2) = __halves2half2(hi[2], hi[3]);
    *(__half2*)(g_xl + i4 * 4)     = __halves2half2(lo[0], lo[1]);
    *(__half2*)(g_xl + i4 * 4 + 2) = __halves2half2(lo[2], lo[3]);
}

__global__ __launch_bounds__(256) void wsplit_kernel(const float* __restrict__ Wq,
                                                     const float* __restrict__ Wk,
                                                     const float* __restrict__ Wv)
{
    int idx = blockIdx.x * blockDim.x + threadIdx.x;
    if (idx >= 3 * DD * DD) return;
    int z = idx / (DD * DD);
    int r = idx - z * (DD * DD);
    const float* W = (z == 0) ? Wq : (z == 1) ? Wk : Wv;
    float v = W[r];
    __half hi = __float2half_rn(v);
    __half lo = __float2half_rn(v - __half2float(hi));
    g_wh[idx] = hi;
    g_wl[idx] = lo;
}

// ---------------------------------------------------------------------------
// q/k/v = x @ W + b via mma.sync; KC=32, 2 stages, 2 CTAs/SM.
// grid (64, 2, 3). z==1 (k) epilogue writes g_kh/g_kl directly.
// ---------------------------------------------------------------------------
#define Q_ITERS   (DD / 32)                 // 8
#define QLDA      40
#define QLDB      136
#define QA_B      (128 * QLDA * 2)          // 10240 per split
#define QB_B      (32 * QLDB * 2)           // 8704 per split
#define QSTAGE_B  (2 * QA_B + 2 * QB_B)     // 37888
#define QNSTAGE   2

__global__ __launch_bounds__(256, 2) void qkvmma_kernel(
    const float* __restrict__ bq, const float* __restrict__ bk,
    const float* __restrict__ bv)
{
    extern __shared__ char smem[];
    const int tid  = threadIdx.x;
    const int wid  = tid >> 5;
    const int lane = tid & 31;
    const int warp_m = wid >> 1;
    const int warp_n = wid & 1;
    const int row0 = blockIdx.x * 128;
    const int n0   = blockIdx.y * 128;
    const int z    = blockIdx.z;
    const __half* Wh = g_wh + (size_t)z * DD * DD;
    const __half* Wl = g_wl + (size_t)z * DD * DD;
    const uint32_t sbase = cvta_smem(smem);

    float acc[2][8][4];
    #pragma unroll
    for (int m = 0; m < 2; m++)
        #pragma unroll
        for (int n = 0; n < 8; n++)
            #pragma unroll
            for (int i = 0; i < 4; i++) acc[m][n][i] = 0.0f;

    #define LOAD_STAGE_Q(st, it)                                                \
    do {                                                                         \
        const int j0 = (it) * 32;                                               \
        const uint32_t sah = sbase + (st) * QSTAGE_B;                           \
        const uint32_t sal = sah + QA_B;                                        \
        const uint32_t sbh = sal + QA_B;                                        \
        const uint32_t sbl = sbh + QB_B;                                        \
        _Pragma("unroll")                                                       \
        for (int u = 0; u < 2; u++) {                                           \
            int c = tid + u * 256;              /* 0..511 */                    \
            int r  = c >> 2;                     /* 0..127 */                   \
            int k8 = (c & 3) * 8;                                               \
            uint32_t off = (uint32_t)(r * QLDA + k8) * 2;                       \
            cp16(sah + off, g_xh + (size_t)(row0 + r) * DD + j0 + k8);          \
            cp16(sal + off, g_xl + (size_t)(row0 + r) * DD + j0 + k8);          \
        }                                                                       \
        _Pragma("unroll")                                                       \
        for (int u = 0; u < 2; u++) {                                           \
            int c = tid + u * 256;                                              \
            int r  = c >> 4;                     /* 0..31 */                    \
            int n8 = (c & 15) * 8;                                              \
            uint32_t off = (uint32_t)(r * QLDB + n8) * 2;                       \
            cp16(sbh + off, Wh + (size_t)(j0 + r) * DD + n0 + n8);              \
            cp16(sbl + off, Wl + (size_t)(j0 + r) * DD + n0 + n8);              \
        }                                                                       \
    } while (0)

    LOAD_STAGE_Q(0, 0); cp_commit();
    LOAD_STAGE_Q(1, 1); cp_commit();

    int buf = 0;
    for (int it = 0; it < Q_ITERS; ++it) {
        cp_wait<1>();
        __syncthreads();
        const uint32_t sah = sbase + buf * QSTAGE_B;
        const uint32_t sal = sah + QA_B;
        const uint32_t sbh = sal + QA_B;
        const uint32_t sbl = sbh + QB_B;

        #pragma unroll
        for (int kk = 0; kk < 2; kk++) {
            uint32_t ah[2][4], al[2][4];
            #pragma unroll
            for (int mf = 0; mf < 2; mf++) {
                int arow = warp_m * 32 + mf * 16 + (lane & 15);
                int acol = kk * 16 + (lane >> 4) * 8;
                uint32_t off = (uint32_t)(arow * QLDA + acol) * 2;
                ldm_x4(sah + off, ah[mf][0], ah[mf][1], ah[mf][2], ah[mf][3]);
                ldm_x4(sal + off, al[mf][0], al[mf][1], al[mf][2], al[mf][3]);
            }
            uint32_t b[8][2];
            #pragma unroll
            for (int nq = 0; nq < 4; nq++) {
                int brow = kk * 16 + (lane & 15);
                int bcol = warp_n * 64 + nq * 16 + (lane >> 4) * 8;
                uint32_t off = (uint32_t)(brow * QLDB + bcol) * 2;
                ldm_x4_t(sbh + off, b[nq*2][0], b[nq*2][1], b[nq*2+1][0], b[nq*2+1][1]);
            }
            #pragma unroll
            for (int mf = 0; mf < 2; mf++)
                #pragma unroll
                for (int nf = 0; nf < 8; nf++) {
                    mma16816(acc[mf][nf], ah[mf], b[nf][0], b[nf][1]);
                    mma16816(acc[mf][nf], al[mf], b[nf][0], b[nf][1]);
                }
            #pragma unroll
            for (int nq = 0; nq < 4; nq++) {
                int brow = kk * 16 + (lane & 15);
                int bcol = warp_n * 64 + nq * 16 + (lane >> 4) * 8;
                uint32_t off = (uint32_t)(brow * QLDB + bcol) * 2;
                ldm_x4_t(sbl + off, b[nq*2][0], b[nq*2][1], b[nq*2+1][0], b[nq*2+1][1]);
            }
            #pragma unroll
            for (int mf = 0; mf < 2; mf++)
                #pragma unroll
                for (int nf = 0; nf < 8; nf++)
                    mma16816(acc[mf][nf], ah[mf], b[nf][0], b[nf][1]);
        }
        __syncthreads();
        if (it + QNSTAGE < Q_ITERS) LOAD_STAGE_Q(buf, it + QNSTAGE);
        cp_commit();
        if (++buf == QNSTAGE) buf = 0;
    }

    const float* bias = (z == 0) ? bq : (z == 1) ? bk : bv;
    #pragma unroll
    for (int mf = 0; mf < 2; mf++) {
        #pragma unroll
        for (int rr = 0; rr < 2; rr++) {
            int row = row0 + warp_m * 32 + mf * 16 + rr * 8 + (lane >> 2);
            #pragma unroll
            for (int nf = 0; nf < 8; nf++) {
                int col = n0 + warp_n * 64 + nf * 8 + (lane & 3) * 2;
                float v0 = acc[mf][nf][rr * 2 + 0] + bias[col];
                float v1 = acc[mf][nf][rr * 2 + 1] + bias[col + 1];
                size_t o = (size_t)row * DD + col;
                if (z == 0) {
                    *(float2*)(g_q + o) = make_float2(v0, v1);
                } else if (z == 2) {
                    *(float2*)(g_v + o) = make_float2(v0, v1);
                } else {
                    __half h0 = __float2half_rn(v0);
                    __half h1 = __float2half_rn(v1);
                    __half l0 = __float2half_rn(v0 - __half2float(h0));
                    __half l1 = __float2half_rn(v1 - __half2float(h1));
                    *(__half2*)(g_kh + o) = __halves2half2(h0, h1);
                    *(__half2*)(g_kl + o) = __halves2half2(l0, l1);
                }
            }
        }
    }
}

// ---------------------------------------------------------------------------
// s partials: A (adj, fp32) loaded DIRECTLY from global per-fragment and
// converted in registers — no A smem, no adj fp16 copy. B (k hi/lo) via
// 3-stage cp.async. Grid (64, 2, 2), 256 threads, 2 CTAs/SM.
// ---------------------------------------------------------------------------
#define S_ITERS   (NN / 2 / 64)             // 64
#define SLDB      136
#define SB_B      (64 * SLDB * 2)           // 17408
#define SSTAGE_B  (2 * SB_B)                // 34816
#define SNSTAGE   3

__global__ __launch_bounds__(256, 2) void smma_kernel(const float* __restrict__ adj)
{
    extern __shared__ char smem[];
    __shared__ float srow[2][128];

    const int tid  = threadIdx.x;
    const int wid  = tid >> 5;
    const int lane = tid & 31;
    const int warp_m = wid >> 1;
    const int warp_n = wid & 1;
    const int row0 = blockIdx.x * 128;
    const int n0   = blockIdx.y * 128;
    const int kbase = blockIdx.z * (NN / 2);
    const uint32_t sbase = cvta_smem(smem);

    // per-thread A base: row = row0 + warp_m*32 + (lane>>2), col = kbase + (lane&3)*2
    const float* Abase = adj + (size_t)(row0 + warp_m * 32 + (lane >> 2)) * NN
                             + kbase + (lane & 3) * 2;

    float acc[2][8][4];
    #pragma unroll
    for (int m = 0; m < 2; m++)
        #pragma unroll
        for (int n = 0; n < 8; n++)
            #pragma unroll
            for (int i = 0; i < 4; i++) acc[m][n][i] = 0.0f;

    #define LOAD_STAGE_S(st, it)                                                \
    do {                                                                         \
        const int j0 = kbase + (it) * 64;                                       \
        const uint32_t sh = sbase + (st) * SSTAGE_B;                            \
        const uint32_t sl = sh + SB_B;                                          \
        _Pragma("unroll")                                                       \
        for (int u = 0; u < 4; u++) {                                           \
            int c = tid + u * 256;                                              \
            int r  = c >> 4;                                                    \
            int n8 = (c & 15) * 8;                                              \
            uint32_t off = (uint32_t)(r * SLDB + n8) * 2;                       \
            cp16(sh + off, g_kh + (size_t)(j0 + r) * DD + n0 + n8);             \
            cp16(sl + off, g_kl + (size_t)(j0 + r) * DD + n0 + n8);             \
        }                                                                       \
    } while (0)

    // A fragment prefetch (fp32, both m-fragments): col offset co within K-half
    float2 af[2][4];
    #define LOAD_A(co)                                                           \
    do {                                                                         \
        _Pragma("unroll")                                                       \
        for (int mf = 0; mf < 2; mf++) {                                        \
            const float* p = Abase + (size_t)(mf * 16) * NN + (co);             \
            af[mf][0] = *(const float2*)(p);                                    \
            af[mf][1] = *(const float2*)(p + (size_t)8 * NN);                   \
            af[mf][2] = *(const float2*)(p + 8);                                \
            af[mf][3] = *(const float2*)(p + (size_t)8 * NN + 8);               \
        }                                                                       \
    } while (0)

    LOAD_STAGE_S(0, 0); cp_commit();
    LOAD_STAGE_S(1, 1); cp_commit();
    LOAD_STAGE_S(2, 2); cp_commit();
    LOAD_A(0);

    int buf = 0;
    for (int it = 0; it < S_ITERS; ++it) {
        cp_wait<2>();
        __syncthreads();
        const uint32_t sh = sbase + buf * SSTAGE_B;
        const uint32_t sl = sh + SB_B;

        #pragma unroll
        for (int kk = 0; kk < 4; kk++) {
            // convert prefetched A to fp16 fragments
            uint32_t a[2][4];
            #pragma unroll
            for (int mf = 0; mf < 2; mf++)
                #pragma unroll
                for (int i = 0; i < 4; i++)
                    a[mf][i] = pack_h2(af[mf][i].x, af[mf][i].y);

            // prefetch next A fragment set
            int co_next = (kk < 3) ? (it * 64 + (kk + 1) * 16)
                                   : ((it + 1 < S_ITERS) ? (it + 1) * 64 : 0);
            LOAD_A(co_next);

            uint32_t b[8][2];
            #pragma unroll
            for (int nq = 0; nq < 4; nq++) {
                int brow = kk * 16 + (lane & 15);
                int bcol = warp_n * 64 + nq * 16 + (lane >> 4) * 8;
                uint32_t off = (uint32_t)(brow * SLDB + bcol) * 2;
                ldm_x4_t(sh + off, b[nq*2][0], b[nq*2][1], b[nq*2+1][0], b[nq*2+1][1]);
            }
            #pragma unroll
            for (int mf = 0; mf < 2; mf++)
                #pragma unroll
                for (int nf = 0; nf < 8; nf++)
                    mma16816(acc[mf][nf], a[mf], b[nf][0], b[nf][1]);
            #pragma unroll
            for (int nq = 0; nq < 4; nq++) {
                int brow = kk * 16 + (lane & 15);
                int bcol = warp_n * 64 + nq * 16 + (lane >> 4) * 8;
                uint32_t off = (uint32_t)(brow * SLDB + bcol) * 2;
                ldm_x4_t(sl + off, b[nq*2][0], b[nq*2][1], b[nq*2+1][0], b[nq*2+1][1]);
            }
            #pragma unroll
            for (int mf = 0; mf < 2; mf++)
                #pragma unroll
                for (int nf = 0; nf < 8; nf++)
                    mma16816(acc[mf][nf], a[mf], b[nf][0], b[nf][1]);
        }
        __syncthreads();
        if (it + SNSTAGE < S_ITERS) LOAD_STAGE_S(buf, it + SNSTAGE);
        cp_commit();
        if (++buf == SNSTAGE) buf = 0;
    }

    // fused epilogue: p[row] = sum_n m[row][n] * q[row][n0+n]
    #pragma unroll
    for (int mf = 0; mf < 2; mf++) {
        #pragma unroll
        for (int rr = 0; rr < 2; rr++) {
            int lrow = warp_m * 32 + mf * 16 + rr * 8 + (lane >> 2);
            int grow = row0 + lrow;
            float p = 0.0f;
            #pragma unroll
            for (int nf = 0; nf < 8; nf++) {
                int gcol = n0 + warp_n * 64 + nf * 8 + (lane & 3) * 2;
                float2 qq = *(const float2*)(g_q + (size_t)grow * DD + gcol);
                p += acc[mf][nf][rr * 2 + 0] * qq.x
                   + acc[mf][nf][rr * 2 + 1] * qq.y;
            }
            p += __shfl_xor_sync(0xffffffffu, p, 1);
            p += __shfl_xor_sync(0xffffffffu, p, 2);
            if ((lane & 3) == 0) srow[warp_n][lrow] = p;
        }
    }
    __syncthreads();
    if (tid < 128)
        g_spart[(size_t)(blockIdx.y * 2 + blockIdx.z) * NN + row0 + tid] =
            srow[0][tid] + srow[1][tid];
}

// ---------------------------------------------------------------------------
// softmax over s = sum of 4 partials
// ---------------------------------------------------------------------------
__global__ __launch_bounds__(1024) void softmax_kernel(float* __restrict__ alpha_out,
                                                       int write_tail)
{
    __shared__ float red[32];
    const int tid = threadIdx.x;
    const int lane = tid & 31;
    const int wid = tid >> 5;

    float lmax = -3.4e38f;
    for (int i = tid; i < NN; i += 1024) {
        float sv = g_spart[i] + g_spart[NN + i] + g_spart[2 * NN + i] + g_spart[3 * NN + i];
        g_s[i] = sv;
        lmax = fmaxf(lmax, sv);
    }
    #pragma unroll
    for (int off = 16; off > 0; off >>= 1)
        lmax = fmaxf(lmax, __shfl_xor_sync(0xffffffffu, lmax, off));
    if (lane == 0) red[wid] = lmax;
    __syncthreads();
    float m = red[lane];
    #pragma unroll
    for (int off = 16; off > 0; off >>= 1)
        m = fmaxf(m, __shfl_xor_sync(0xffffffffu, m, off));
    __syncthreads();

    float lsum = 0.0f;
    for (int i = tid; i < NN; i += 1024) {
        float e = expf(g_s[i] - m);
        g_alpha[i] = e;
        lsum += e;
    }
    #pragma unroll
    for (int off = 16; off > 0; off >>= 1)
        lsum += __shfl_xor_sync(0xffffffffu, lsum, off);
    if (lane == 0) red[wid] = lsum;
    __syncthreads();
    float ssum = red[lane];
    #pragma unroll
    for (int off = 16; off > 0; off >>= 1)
        ssum += __shfl_xor_sync(0xffffffffu, ssum, off);
    float inv = 1.0f / ssum;

    for (int i = tid; i < NN; i += 1024) {
        float a = g_alpha[i] * inv;
        g_alpha[i] = a;
        if (write_tail) alpha_out[i] = a;
    }
}

// ---------------------------------------------------------------------------
// out[i, :] = alpha[i] * v[i, :]
// ---------------------------------------------------------------------------
__global__ __launch_bounds__(256) void out_kernel(float* __restrict__ out)
{
    int idx = blockIdx.x * blockDim.x + threadIdx.x;
    const int total4 = NN * DD / 4;
    if (idx >= total4) return;
    int row = (idx * 4) / DD;
    float a = g_alpha[row];
    float4 v4 = *(const float4*)(g_v + (size_t)idx * 4);
    v4.x *= a; v4.y *= a; v4.z *= a; v4.w *= a;
    *(float4*)(out + (size_t)idx * 4) = v4;
}

// ---------------------------------------------------------------------------
extern "C" void kernel_launch(void* const* d_in, const int* in_sizes, int n_in,
                              void* d_out, int out_size) {
    const float* x   = (const float*)d_in[0];
    const float* adj = (const float*)d_in[1];
    const float* Wq  = (const float*)d_in[2];
    const float* bq  = (const float*)d_in[3];
    const float* Wk  = (const float*)d_in[4];
    const float* bk  = (const float*)d_in[5];
    const float* Wv  = (const float*)d_in[6];
    const float* bv  = (const float*)d_in[7];
    float* out = (float*)d_out;

    // x, W -> fp16 hi/lo
    {
        size_t total4 = (size_t)NN * DD / 4;
        xsplit_kernel<<<(unsigned)((total4 + 255) / 256), 256>>>(x);
        wsplit_kernel<<<(3 * DD * DD + 255) / 256, 256>>>(Wq, Wk, Wv);
    }

    // q/k/v projections via mma (k written directly as hi/lo splits)
    cudaFuncSetAttribute(qkvmma_kernel, cudaFuncAttributeMaxDynamicSharedMemorySize,
                         QNSTAGE * QSTAGE_B);
    dim3 gq(NN / 128, 2, 3);
    qkvmma_kernel<<<gq, 256, QNSTAGE * QSTAGE_B>>>(bq, bk, bv);

    // s partials: adj fp32 direct-from-global A + fp16 B, fused rowdot epilogue
    cudaFuncSetAttribute(smma_kernel, cudaFuncAttributeMaxDynamicSharedMemorySize,
                         SNSTAGE * SSTAGE_B);
    dim3 gs(NN / 128, 2, 2);
    smma_kernel<<<gs, 256, SNSTAGE * SSTAGE_B>>>(adj);

    // softmax
    int write_tail = (out_size >= NN * DD + NN) ? 1 : 0;
    softmax_kernel<<<1, 1024>>>(out + (size_t)NN * DD, write_tail);

    // out = alpha[:,None] * v
    int total4 = NN * DD / 4;
    out_kernel<<<(total4 + 255) / 256, 256>>>(out);
}

// round 9
// speedup vs baseline: 1.1703x; 1.1703x over previous
#include <cuda_runtime.h>
#include <cuda_fp16.h>
#include <cstdint>

#define NN 8192
#define DD 256

// ---------------- scratch (device globals; no allocation allowed) ----------
__device__ float  g_q[NN * DD];
__device__ float  g_v[NN * DD];
__device__ __half g_adj_h[(size_t)NN * NN];   // adj in fp16 (exact: 0/1)
__device__ __half g_xh[NN * DD];              // x hi split
__device__ __half g_xl[NN * DD];              // x lo split
__device__ __half g_wh[3 * DD * DD];          // Wq|Wk|Wv hi split
__device__ __half g_wl[3 * DD * DD];          // Wq|Wk|Wv lo split
__device__ __half g_kh[NN * DD];              // k hi split [j][d]
__device__ __half g_kl[NN * DD];              // k lo split
__device__ float  g_spart[4 * NN];            // deterministic partials
__device__ float  g_s[NN];
__device__ float  g_alpha[NN];

// ---------------- PTX helpers (base sm_80+ ISA only) ------------------------
__device__ __forceinline__ uint32_t cvta_smem(const void* p) {
    uint32_t a;
    asm("{ .reg .u64 t; cvta.to.shared.u64 t, %1; cvt.u32.u64 %0, t; }"
        : "=r"(a) : "l"(p));
    return a;
}
__device__ __forceinline__ void cp16(uint32_t dst, const void* src) {
    asm volatile("cp.async.cg.shared.global [%0], [%1], 16;" :: "r"(dst), "l"(src));
}
__device__ __forceinline__ void cp_commit() {
    asm volatile("cp.async.commit_group;" ::: "memory");
}
template <int N>
__device__ __forceinline__ void cp_wait() {
    asm volatile("cp.async.wait_group %0;" :: "n"(N) : "memory");
}
__device__ __forceinline__ void ldm_x4(uint32_t addr, uint32_t& r0, uint32_t& r1,
                                       uint32_t& r2, uint32_t& r3) {
    asm volatile("ldmatrix.sync.aligned.m8n8.x4.shared.b16 {%0,%1,%2,%3}, [%4];"
                 : "=r"(r0), "=r"(r1), "=r"(r2), "=r"(r3) : "r"(addr));
}
__device__ __forceinline__ void ldm_x4_t(uint32_t addr, uint32_t& r0, uint32_t& r1,
                                         uint32_t& r2, uint32_t& r3) {
    asm volatile("ldmatrix.sync.aligned.m8n8.x4.trans.shared.b16 {%0,%1,%2,%3}, [%4];"
                 : "=r"(r0), "=r"(r1), "=r"(r2), "=r"(r3) : "r"(addr));
}
__device__ __forceinline__ void mma16816(float* c, const uint32_t* a,
                                         uint32_t b0, uint32_t b1) {
    asm volatile(
        "mma.sync.aligned.m16n8k16.row.col.f32.f16.f16.f32 "
        "{%0,%1,%2,%3}, {%4,%5,%6,%7}, {%8,%9}, {%0,%1,%2,%3};"
        : "+f"(c[0]), "+f"(c[1]), "+f"(c[2]), "+f"(c[3])
        : "r"(a[0]), "r"(a[1]), "r"(a[2]), "r"(a[3]), "r"(b0), "r"(b1));
}

// ---------------------------------------------------------------------------
// Converters
// ---------------------------------------------------------------------------
__global__ __launch_bounds__(256) void adj2h_kernel(const float* __restrict__ adj)
{
    size_t i4 = (size_t)blockIdx.x * blockDim.x + threadIdx.x;
    const size_t total4 = (size_t)NN * NN / 4;
    if (i4 >= total4) return;
    float4 a = *(const float4*)(adj + i4 * 4);
    *(__half2*)(g_adj_h + i4 * 4)     = __floats2half2_rn(a.x, a.y);
    *(__half2*)(g_adj_h + i4 * 4 + 2) = __floats2half2_rn(a.z, a.w);
}

__global__ __launch_bounds__(256) void xsplit_kernel(const float* __restrict__ x)
{
    size_t i4 = (size_t)blockIdx.x * blockDim.x + threadIdx.x;
    const size_t total4 = (size_t)NN * DD / 4;
    if (i4 >= total4) return;
    float4 xv = *(const float4*)(x + i4 * 4);
    float vs[4] = {xv.x, xv.y, xv.z, xv.w};
    __half hi[4], lo[4];
    #pragma unroll
    for (int i = 0; i < 4; i++) {
        hi[i] = __float2half_rn(vs[i]);
        lo[i] = __float2half_rn(vs[i] - __half2float(hi[i]));
    }
    *(__half2*)(g_xh + i4 * 4)     = __halves2half2(hi[0], hi[1]);
    *(__half2*)(g_xh + i4 * 4 + 2) = __halves2half2(hi[2], hi[3]);
    *(__half2*)(g_xl + i4 * 4)     = __halves2half2(lo[0], lo[1]);
    *(__half2*)(g_xl + i4 * 4 + 2) = __halves2half2(lo[2], lo[3]);
}

__global__ __launch_bounds__(256) void wsplit_kernel(const float* __restrict__ Wq,
                                                     const float* __restrict__ Wk,
                                                     const float* __restrict__ Wv)
{
    int idx = blockIdx.x * blockDim.x + threadIdx.x;
    if (idx >= 3 * DD * DD) return;
    int z = idx / (DD * DD);
    int r = idx - z * (DD * DD);
    const float* W = (z == 0) ? Wq : (z == 1) ? Wk : Wv;
    float v = W[r];
    __half hi = __float2half_rn(v);
    __half lo = __float2half_rn(v - __half2float(hi));
    g_wh[idx] = hi;
    g_wl[idx] = lo;
}

// ---------------------------------------------------------------------------
// q/k/v = x @ W + b via mma.sync; KC=32, 2 stages, 2 CTAs/SM.
// grid (64, 2, 3). z==1 (k) epilogue writes g_kh/g_kl directly.
// ---------------------------------------------------------------------------
#define Q_ITERS   (DD / 32)                 // 8
#define QLDA      40
#define QLDB      136
#define QA_B      (128 * QLDA * 2)          // 10240 per split
#define QB_B      (32 * QLDB * 2)           // 8704 per split
#define QSTAGE_B  (2 * QA_B + 2 * QB_B)     // 37888
#define QNSTAGE   2

__global__ __launch_bounds__(256, 2) void qkvmma_kernel(
    const float* __restrict__ bq, const float* __restrict__ bk,
    const float* __restrict__ bv)
{
    extern __shared__ char smem[];
    const int tid  = threadIdx.x;
    const int wid  = tid >> 5;
    const int lane = tid & 31;
    const int warp_m = wid >> 1;
    const int warp_n = wid & 1;
    const int row0 = blockIdx.x * 128;
    const int n0   = blockIdx.y * 128;
    const int z    = blockIdx.z;
    const __half* Wh = g_wh + (size_t)z * DD * DD;
    const __half* Wl = g_wl + (size_t)z * DD * DD;
    const uint32_t sbase = cvta_smem(smem);

    float acc[2][8][4];
    #pragma unroll
    for (int m = 0; m < 2; m++)
        #pragma unroll
        for (int n = 0; n < 8; n++)
            #pragma unroll
            for (int i = 0; i < 4; i++) acc[m][n][i] = 0.0f;

    #define LOAD_STAGE_Q(st, it)                                                \
    do {                                                                         \
        const int j0 = (it) * 32;                                               \
        const uint32_t sah = sbase + (st) * QSTAGE_B;                           \
        const uint32_t sal = sah + QA_B;                                        \
        const uint32_t sbh = sal + QA_B;                                        \
        const uint32_t sbl = sbh + QB_B;                                        \
        _Pragma("unroll")                                                       \
        for (int u = 0; u < 2; u++) {                                           \
            int c = tid + u * 256;              /* 0..511 */                    \
            int r  = c >> 2;                     /* 0..127 */                   \
            int k8 = (c & 3) * 8;                                               \
            uint32_t off = (uint32_t)(r * QLDA + k8) * 2;                       \
            cp16(sah + off, g_xh + (size_t)(row0 + r) * DD + j0 + k8);          \
            cp16(sal + off, g_xl + (size_t)(row0 + r) * DD + j0 + k8);          \
        }                                                                       \
        _Pragma("unroll")                                                       \
        for (int u = 0; u < 2; u++) {                                           \
            int c = tid + u * 256;                                              \
            int r  = c >> 4;                     /* 0..31 */                    \
            int n8 = (c & 15) * 8;                                              \
            uint32_t off = (uint32_t)(r * QLDB + n8) * 2;                       \
            cp16(sbh + off, Wh + (size_t)(j0 + r) * DD + n0 + n8);              \
            cp16(sbl + off, Wl + (size_t)(j0 + r) * DD + n0 + n8);              \
        }                                                                       \
    } while (0)

    LOAD_STAGE_Q(0, 0); cp_commit();
    LOAD_STAGE_Q(1, 1); cp_commit();

    int buf = 0;
    for (int it = 0; it < Q_ITERS; ++it) {
        cp_wait<1>();
        __syncthreads();
        const uint32_t sah = sbase + buf * QSTAGE_B;
        const uint32_t sal = sah + QA_B;
        const uint32_t sbh = sal + QA_B;
        const uint32_t sbl = sbh + QB_B;

        #pragma unroll
        for (int kk = 0; kk < 2; kk++) {
            uint32_t ah[2][4], al[2][4];
            #pragma unroll
            for (int mf = 0; mf < 2; mf++) {
                int arow = warp_m * 32 + mf * 16 + (lane & 15);
                int acol = kk * 16 + (lane >> 4) * 8;
                uint32_t off = (uint32_t)(arow * QLDA + acol) * 2;
                ldm_x4(sah + off, ah[mf][0], ah[mf][1], ah[mf][2], ah[mf][3]);
                ldm_x4(sal + off, al[mf][0], al[mf][1], al[mf][2], al[mf][3]);
            }
            uint32_t b[8][2];
            #pragma unroll
            for (int nq = 0; nq < 4; nq++) {
                int brow = kk * 16 + (lane & 15);
                int bcol = warp_n * 64 + nq * 16 + (lane >> 4) * 8;
                uint32_t off = (uint32_t)(brow * QLDB + bcol) * 2;
                ldm_x4_t(sbh + off, b[nq*2][0], b[nq*2][1], b[nq*2+1][0], b[nq*2+1][1]);
            }
            #pragma unroll
            for (int mf = 0; mf < 2; mf++)
                #pragma unroll
                for (int nf = 0; nf < 8; nf++) {
                    mma16816(acc[mf][nf], ah[mf], b[nf][0], b[nf][1]);
                    mma16816(acc[mf][nf], al[mf], b[nf][0], b[nf][1]);
                }
            #pragma unroll
            for (int nq = 0; nq < 4; nq++) {
                int brow = kk * 16 + (lane & 15);
                int bcol = warp_n * 64 + nq * 16 + (lane >> 4) * 8;
                uint32_t off = (uint32_t)(brow * QLDB + bcol) * 2;
                ldm_x4_t(sbl + off, b[nq*2][0], b[nq*2][1], b[nq*2+1][0], b[nq*2+1][1]);
            }
            #pragma unroll
            for (int mf = 0; mf < 2; mf++)
                #pragma unroll
                for (int nf = 0; nf < 8; nf++)
                    mma16816(acc[mf][nf], ah[mf], b[nf][0], b[nf][1]);
        }
        __syncthreads();
        if (it + QNSTAGE < Q_ITERS) LOAD_STAGE_Q(buf, it + QNSTAGE);
        cp_commit();
        if (++buf == QNSTAGE) buf = 0;
    }

    const float* bias = (z == 0) ? bq : (z == 1) ? bk : bv;
    #pragma unroll
    for (int mf = 0; mf < 2; mf++) {
        #pragma unroll
        for (int rr = 0; rr < 2; rr++) {
            int row = row0 + warp_m * 32 + mf * 16 + rr * 8 + (lane >> 2);
            #pragma unroll
            for (int nf = 0; nf < 8; nf++) {
                int col = n0 + warp_n * 64 + nf * 8 + (lane & 3) * 2;
                float v0 = acc[mf][nf][rr * 2 + 0] + bias[col];
                float v1 = acc[mf][nf][rr * 2 + 1] + bias[col + 1];
                size_t o = (size_t)row * DD + col;
                if (z == 0) {
                    *(float2*)(g_q + o) = make_float2(v0, v1);
                } else if (z == 2) {
                    *(float2*)(g_v + o) = make_float2(v0, v1);
                } else {
                    __half h0 = __float2half_rn(v0);
                    __half h1 = __float2half_rn(v1);
                    __half l0 = __float2half_rn(v0 - __half2float(h0));
                    __half l1 = __float2half_rn(v1 - __half2float(h1));
                    *(__half2*)(g_kh + o) = __halves2half2(h0, h1);
                    *(__half2*)(g_kl + o) = __halves2half2(l0, l1);
                }
            }
        }
    }
}

// ---------------------------------------------------------------------------
// s partials via fp16 mma.sync, adj fp16 staged through smem (cp.async).
// Grid (64 Mtiles, 2 Ntiles, 2 Khalves), 256 threads, 2 CTAs/SM, KC=64.
// (Reverted to the round-6 configuration that measured ~180us.)
// ---------------------------------------------------------------------------
#define S_ITERS   (NN / 2 / 64)             // 64
#define SLDA      72
#define SLDB      136
#define SA_B      (128 * SLDA * 2)          // 18432
#define SB_B      (64 * SLDB * 2)           // 17408
#define SSTAGE_B  (SA_B + 2 * SB_B)         // 53248
#define SNSTAGE   2

__global__ __launch_bounds__(256, 2) void smma_kernel()
{
    extern __shared__ char smem[];
    __shared__ float srow[2][128];

    const int tid  = threadIdx.x;
    const int wid  = tid >> 5;
    const int lane = tid & 31;
    const int warp_m = wid >> 1;
    const int warp_n = wid & 1;
    const int row0 = blockIdx.x * 128;
    const int n0   = blockIdx.y * 128;
    const int kbase = blockIdx.z * (NN / 2);
    const uint32_t sbase = cvta_smem(smem);

    float acc[2][8][4];
    #pragma unroll
    for (int m = 0; m < 2; m++)
        #pragma unroll
        for (int n = 0; n < 8; n++)
            #pragma unroll
            for (int i = 0; i < 4; i++) acc[m][n][i] = 0.0f;

    #define LOAD_STAGE_S(st, it)                                                \
    do {                                                                         \
        const int j0 = kbase + (it) * 64;                                       \
        const uint32_t sa = sbase + (st) * SSTAGE_B;                            \
        const uint32_t sh = sa + SA_B;                                          \
        const uint32_t sl = sh + SB_B;                                          \
        _Pragma("unroll")                                                       \
        for (int u = 0; u < 4; u++) {                                           \
            int c = tid + u * 256;                                              \
            int r  = c >> 3;                                                    \
            int k8 = (c & 7) * 8;                                               \
            cp16(sa + (uint32_t)(r * SLDA + k8) * 2,                            \
                 g_adj_h + (size_t)(row0 + r) * NN + j0 + k8);                  \
        }                                                                       \
        _Pragma("unroll")                                                       \
        for (int u = 0; u < 4; u++) {                                           \
            int c = tid + u * 256;                                              \
            int r  = c >> 4;                                                    \
            int n8 = (c & 15) * 8;                                              \
            uint32_t off = (uint32_t)(r * SLDB + n8) * 2;                       \
            cp16(sh + off, g_kh + (size_t)(j0 + r) * DD + n0 + n8);             \
            cp16(sl + off, g_kl + (size_t)(j0 + r) * DD + n0 + n8);             \
        }                                                                       \
    } while (0)

    LOAD_STAGE_S(0, 0); cp_commit();
    LOAD_STAGE_S(1, 1); cp_commit();

    int buf = 0;
    for (int it = 0; it < S_ITERS; ++it) {
        cp_wait<1>();
        __syncthreads();
        const uint32_t sa = sbase + buf * SSTAGE_B;
        const uint32_t sh = sa + SA_B;
        const uint32_t sl = sh + SB_B;

        #pragma unroll
        for (int kk = 0; kk < 4; kk++) {
            uint32_t a[2][4];
            #pragma unroll
            for (int mf = 0; mf < 2; mf++) {
                int arow = warp_m * 32 + mf * 16 + (lane & 15);
                int acol = kk * 16 + (lane >> 4) * 8;
                ldm_x4(sa + (uint32_t)(arow * SLDA + acol) * 2,
                       a[mf][0], a[mf][1], a[mf][2], a[mf][3]);
            }
            uint32_t b[8][2];
            #pragma unroll
            for (int nq = 0; nq < 4; nq++) {
                int brow = kk * 16 + (lane & 15);
                int bcol = warp_n * 64 + nq * 16 + (lane >> 4) * 8;
                uint32_t off = (uint32_t)(brow * SLDB + bcol) * 2;
                ldm_x4_t(sh + off, b[nq*2][0], b[nq*2][1], b[nq*2+1][0], b[nq*2+1][1]);
            }
            #pragma unroll
            for (int mf = 0; mf < 2; mf++)
                #pragma unroll
                for (int nf = 0; nf < 8; nf++)
                    mma16816(acc[mf][nf], a[mf], b[nf][0], b[nf][1]);
            #pragma unroll
            for (int nq = 0; nq < 4; nq++) {
                int brow = kk * 16 + (lane & 15);
                int bcol = warp_n * 64 + nq * 16 + (lane >> 4) * 8;
                uint32_t off = (uint32_t)(brow * SLDB + bcol) * 2;
                ldm_x4_t(sl + off, b[nq*2][0], b[nq*2][1], b[nq*2+1][0], b[nq*2+1][1]);
            }
            #pragma unroll
            for (int mf = 0; mf < 2; mf++)
                #pragma unroll
                for (int nf = 0; nf < 8; nf++)
                    mma16816(acc[mf][nf], a[mf], b[nf][0], b[nf][1]);
        }
        __syncthreads();
        if (it + SNSTAGE < S_ITERS) LOAD_STAGE_S(buf, it + SNSTAGE);
        cp_commit();
        if (++buf == SNSTAGE) buf = 0;
    }

    // fused epilogue: p[row] = sum_n m[row][n] * q[row][n0+n]
    #pragma unroll
    for (int mf = 0; mf < 2; mf++) {
        #pragma unroll
        for (int rr = 0; rr < 2; rr++) {
            int lrow = warp_m * 32 + mf * 16 + rr * 8 + (lane >> 2);
            int grow = row0 + lrow;
            float p = 0.0f;
            #pragma unroll
            for (int nf = 0; nf < 8; nf++) {
                int gcol = n0 + warp_n * 64 + nf * 8 + (lane & 3) * 2;
                float2 qq = *(const float2*)(g_q + (size_t)grow * DD + gcol);
                p += acc[mf][nf][rr * 2 + 0] * qq.x
                   + acc[mf][nf][rr * 2 + 1] * qq.y;
            }
            p += __shfl_xor_sync(0xffffffffu, p, 1);
            p += __shfl_xor_sync(0xffffffffu, p, 2);
            if ((lane & 3) == 0) srow[warp_n][lrow] = p;
        }
    }
    __syncthreads();
    if (tid < 128)
        g_spart[(size_t)(blockIdx.y * 2 + blockIdx.z) * NN + row0 + tid] =
            srow[0][tid] + srow[1][tid];
}

// ---------------------------------------------------------------------------
// softmax over s = sum of 4 partials
// ---------------------------------------------------------------------------
__global__ __launch_bounds__(1024) void softmax_kernel(float* __restrict__ alpha_out,
                                                       int write_tail)
{
    __shared__ float red[32];
    const int tid = threadIdx.x;
    const int lane = tid & 31;
    const int wid = tid >> 5;

    float lmax = -3.4e38f;
    for (int i = tid; i < NN; i += 1024) {
        float sv = g_spart[i] + g_spart[NN + i] + g_spart[2 * NN + i] + g_spart[3 * NN + i];
        g_s[i] = sv;
        lmax = fmaxf(lmax, sv);
    }
    #pragma unroll
    for (int off = 16; off > 0; off >>= 1)
        lmax = fmaxf(lmax, __shfl_xor_sync(0xffffffffu, lmax, off));
    if (lane == 0) red[wid] = lmax;
    __syncthreads();
    float m = red[lane];
    #pragma unroll
    for (int off = 16; off > 0; off >>= 1)
        m = fmaxf(m, __shfl_xor_sync(0xffffffffu, m, off));
    __syncthreads();

    float lsum = 0.0f;
    for (int i = tid; i < NN; i += 1024) {
        float e = expf(g_s[i] - m);
        g_alpha[i] = e;
        lsum += e;
    }
    #pragma unroll
    for (int off = 16; off > 0; off >>= 1)
        lsum += __shfl_xor_sync(0xffffffffu, lsum, off);
    if (lane == 0) red[wid] = lsum;
    __syncthreads();
    float ssum = red[lane];
    #pragma unroll
    for (int off = 16; off > 0; off >>= 1)
        ssum += __shfl_xor_sync(0xffffffffu, ssum, off);
    float inv = 1.0f / ssum;

    for (int i = tid; i < NN; i += 1024) {
        float a = g_alpha[i] * inv;
        g_alpha[i] = a;
        if (write_tail) alpha_out[i] = a;
    }
}

// ---------------------------------------------------------------------------
// out[i, :] = alpha[i] * v[i, :]
// ---------------------------------------------------------------------------
__global__ __launch_bounds__(256) void out_kernel(float* __restrict__ out)
{
    int idx = blockIdx.x * blockDim.x + threadIdx.x;
    const int total4 = NN * DD / 4;
    if (idx >= total4) return;
    int row = (idx * 4) / DD;
    float a = g_alpha[row];
    float4 v4 = *(const float4*)(g_v + (size_t)idx * 4);
    v4.x *= a; v4.y *= a; v4.z *= a; v4.w *= a;
    *(float4*)(out + (size_t)idx * 4) = v4;
}

// ---------------------------------------------------------------------------
extern "C" void kernel_launch(void* const* d_in, const int* in_sizes, int n_in,
                              void* d_out, int out_size) {
    const float* x   = (const float*)d_in[0];
    const float* adj = (const float*)d_in[1];
    const float* Wq  = (const float*)d_in[2];
    const float* bq  = (const float*)d_in[3];
    const float* Wk  = (const float*)d_in[4];
    const float* bk  = (const float*)d_in[5];
    const float* Wv  = (const float*)d_in[6];
    const float* bv  = (const float*)d_in[7];
    float* out = (float*)d_out;

    // adj -> fp16 (largest convert; bandwidth-bound)
    {
        size_t total4 = (size_t)NN * NN / 4;
        adj2h_kernel<<<(unsigned)((total4 + 255) / 256), 256>>>(adj);
    }
    // x, W -> fp16 hi/lo
    {
        size_t total4 = (size_t)NN * DD / 4;
        xsplit_kernel<<<(unsigned)((total4 + 255) / 256), 256>>>(x);
        wsplit_kernel<<<(3 * DD * DD + 255) / 256, 256>>>(Wq, Wk, Wv);
    }

    // q/k/v projections via mma (k written directly as hi/lo splits)
    cudaFuncSetAttribute(qkvmma_kernel, cudaFuncAttributeMaxDynamicSharedMemorySize,
                         QNSTAGE * QSTAGE_B);
    dim3 gq(NN / 128, 2, 3);
    qkvmma_kernel<<<gq, 256, QNSTAGE * QSTAGE_B>>>(bq, bk, bv);

    // s partials via fp16 mma GEMM + fused rowdot epilogue
    cudaFuncSetAttribute(smma_kernel, cudaFuncAttributeMaxDynamicSharedMemorySize,
                         SNSTAGE * SSTAGE_B);
    dim3 gs(NN / 128, 2, 2);
    smma_kernel<<<gs, 256, SNSTAGE * SSTAGE_B>>>();

    // softmax
    int write_tail = (out_size >= NN * DD + NN) ? 1 : 0;
    softmax_kernel<<<1, 1024>>>(out + (size_t)NN * DD, write_tail);

    // out = alpha[:,None] * v
    int total4 = NN * DD / 4;
    out_kernel<<<(total4 + 255) / 256, 256>>>(out);
}